// round 9
// baseline (speedup 1.0000x reference)
#include <cuda_runtime.h>

#define NUM_CAMS 6
#define C_FEAT   64
#define HF       16
#define WF       44
#define P_TOTAL  (8 * 128 * 128)                      // 131072
#define FEAT_ELEMS (NUM_CAMS * C_FEAT * HF * WF)      // 270336

#define PTS_PER_BLK 128
#define TASKS (PTS_PER_BLK * NUM_CAMS)                // 768

#define PK_BASE_MASK 0x7FFFF
#define PK_DX_BIT    (1 << 20)
#define PK_DY_BIT    (1 << 21)

// Precomputed per-camera projection (rows 0..2 of cam2img @ ego2cam)
__device__ float g_proj[NUM_CAMS][12];
// NHWC-transposed features: [cam][y][x][c], c contiguous (256B per pixel)
__device__ float g_feat_t[NUM_CAMS * HF * WF * C_FEAT];

// ---------------------------------------------------------------------------
// Prep: transpose (n,c,y,x) -> (n,y,x,c); block 0 also computes projections.
// ---------------------------------------------------------------------------
__global__ void prep_kernel(const float* __restrict__ in,
                            const float* __restrict__ ego2cam,
                            const float* __restrict__ cam2img) {
    int idx = blockIdx.x * blockDim.x + threadIdx.x;
    if (idx < FEAT_ELEMS) {
        int x = idx % WF;
        int t = idx / WF;
        int y = t % HF;  t /= HF;
        int c = t % C_FEAT;
        int n = t / C_FEAT;
        g_feat_t[(((n * HF + y) * WF) + x) * C_FEAT + c] = in[idx];
    }
    if (blockIdx.x == 0 && threadIdx.x < NUM_CAMS * 12) {
        int t = threadIdx.x;
        int n = t / 12;
        int r = (t % 12) / 4;
        int c = t % 4;
        float s = 0.f;
        #pragma unroll
        for (int k = 0; k < 4; k++)
            s += cam2img[n * 16 + r * 4 + k] * ego2cam[n * 16 + k * 4 + c];
        g_proj[n][r * 4 + c] = s;
    }
}

// ---------------------------------------------------------------------------
// Fuse: 128 points per block -> grid 1024 -> single resident wave (no tail).
//   Stage 1 : each (point,cam) projection once; valid entries write weights
//             (float4) + packed corner info (1 int); cam bitmask via atomicOr.
//   Stage 2 : 4 chunks of 32 points; 16 lanes/point, ffs loop over valid cams
//             only; 4x LDG.128 per cam; acc scaled by 1/popc(mask).
//   Writeout: smem-staged per chunk, STG.128 along points.
// ---------------------------------------------------------------------------
__global__ void __launch_bounds__(256)
fuse_kernel(const float* __restrict__ vox, float* __restrict__ out) {
    __shared__ float4 s_w[TASKS];               // 12 KB   [n*128+pt]
    __shared__ int    s_pk[TASKS];              // 3 KB    [n*128+pt]
    __shared__ int    s_mask[PTS_PER_BLK];      // 512 B
    __shared__ float  s_out[32][65];            // 8.25 KB, padded rows

    int tid   = threadIdx.x;
    int pbase = blockIdx.x * PTS_PER_BLK;

    if (tid < PTS_PER_BLK) s_mask[tid] = 0;
    __syncthreads();

    // ---------------- Stage 1: projections, once per (point, cam) ----------
    #pragma unroll
    for (int k = 0; k < 3; k++) {
        int task = k * 256 + tid;
        int pt = task & (PTS_PER_BLK - 1);
        int n  = task >> 7;                      // 0..5  (task = n*128+pt)
        int p  = pbase + pt;

        float px = vox[p];
        float py = vox[P_TOTAL + p];
        float pz = vox[2 * P_TOTAL + p];

        const float* M = g_proj[n];
        float uu = M[0] * px + M[1] * py + M[2]  * pz + M[3];
        float vv = M[4] * px + M[5] * py + M[6]  * pz + M[7];
        float dd = M[8] * px + M[9] * py + M[10] * pz + M[11];

        float inv = 1.0f / (dd + 1e-6f);
        float u = uu * inv;
        float v = vv * inv;

        bool valid = (dd > 0.1f) && (u >= 0.f) && (u <= 703.f)
                                 && (v >= 0.f) && (v <= 255.f);
        if (valid) {
            float x = u * (1.0f / 16.0f);
            float y = v * (1.0f / 16.0f);
            float x0f = floorf(x);
            float y0f = floorf(y);
            float wx1 = x - x0f, wy1 = y - y0f;
            float wx0 = 1.f - wx1, wy0 = 1.f - wy1;
            int x0 = (int)x0f;
            int y0 = (int)y0f;

            int dxb = PK_DX_BIT, dyb = PK_DY_BIT;
            if (x0 + 1 >= WF) { wx1 = 0.f; dxb = 0; }
            if (y0 + 1 >= HF) { wy1 = 0.f; dyb = 0; }

            int base = ((n * HF + y0) * WF + x0) * C_FEAT;   // < 2^19
            s_w[task]  = make_float4(wx0 * wy0, wx1 * wy0, wx0 * wy1, wx1 * wy1);
            s_pk[task] = base | dxb | dyb;
            atomicOr(&s_mask[pt], 1 << n);
        }
    }
    __syncthreads();

    // ---------------- Stage 2 + writeout, 4 chunks of 32 points -------------
    int lane = tid & 31;
    int wrp  = tid >> 5;          // 0..7
    int half = lane >> 4;
    int l    = lane & 15;         // channel group
    const float* fB = g_feat_t + 4 * l;

    #pragma unroll
    for (int chunk = 0; chunk < 4; chunk++) {
        #pragma unroll
        for (int it = 0; it < 2; it++) {
            int pt  = chunk * 32 + wrp * 4 + it * 2 + half;  // global pt
            int row = pt - chunk * 32;                        // s_out row

            float4 acc = make_float4(0.f, 0.f, 0.f, 0.f);

            int m = s_mask[pt];
            float rden = 1.0f / (float)__popc(m | (m == 0));

            while (m) {
                int n = __ffs(m) - 1;
                m &= m - 1;
                int idx = n * PTS_PER_BLK + pt;
                float4 wg = s_w[idx];
                int    pk = s_pk[idx];
                int base  = pk & PK_BASE_MASK;
                int dx    = (pk & PK_DX_BIT) ? C_FEAT : 0;
                int dy    = (pk & PK_DY_BIT) ? WF * C_FEAT : 0;

                float4 a = *(const float4*)(fB + base);
                float4 b = *(const float4*)(fB + base + dx);
                float4 g = *(const float4*)(fB + base + dy);
                float4 h = *(const float4*)(fB + base + dy + dx);

                acc.x = fmaf(wg.x, a.x, fmaf(wg.y, b.x, fmaf(wg.z, g.x, fmaf(wg.w, h.x, acc.x))));
                acc.y = fmaf(wg.x, a.y, fmaf(wg.y, b.y, fmaf(wg.z, g.y, fmaf(wg.w, h.y, acc.y))));
                acc.z = fmaf(wg.x, a.z, fmaf(wg.y, b.z, fmaf(wg.z, g.z, fmaf(wg.w, h.z, acc.z))));
                acc.w = fmaf(wg.x, a.w, fmaf(wg.y, b.w, fmaf(wg.z, g.w, fmaf(wg.w, h.w, acc.w))));
            }

            // scalar STS (row stride 65 floats: not 16B aligned for odd rows)
            s_out[row][4 * l + 0] = acc.x * rden;
            s_out[row][4 * l + 1] = acc.y * rden;
            s_out[row][4 * l + 2] = acc.z * rden;
            s_out[row][4 * l + 3] = acc.w * rden;
        }

        __syncthreads();

        // Coalesced vectorized writeout of this 32-point chunk:
        // 64 channels x 32 points, STG.128 along the point dimension.
        #pragma unroll
        for (int k = 0; k < 2; k++) {
            int flat = k * 256 + tid;       // 0..511 float4 tiles
            int c = flat >> 3;              // 0..63
            int q = flat & 7;               // point quad 0..7
            float4 r;
            r.x = s_out[4 * q + 0][c];
            r.y = s_out[4 * q + 1][c];
            r.z = s_out[4 * q + 2][c];
            r.w = s_out[4 * q + 3][c];
            *(float4*)(out + c * P_TOTAL + pbase + chunk * 32 + 4 * q) = r;
        }

        __syncthreads();   // protect s_out before next chunk's STS
    }
}

// ---------------------------------------------------------------------------
extern "C" void kernel_launch(void* const* d_in, const int* in_sizes, int n_in,
                              void* d_out, int out_size) {
    const float* img_feats = (const float*)d_in[0];   // (6,64,16,44)
    const float* ego2cam   = (const float*)d_in[1];   // (6,4,4)
    const float* cam2img   = (const float*)d_in[2];   // (6,4,4)
    const float* vox       = (const float*)d_in[3];   // (3,8,128,128)
    float* out = (float*)d_out;                       // (1,64,8,128,128)

    prep_kernel<<<(FEAT_ELEMS + 255) / 256, 256>>>(img_feats, ego2cam, cam2img);
    fuse_kernel<<<P_TOTAL / PTS_PER_BLK, 256>>>(vox, out);
}

// round 10
// speedup vs baseline: 1.1652x; 1.1652x over previous
#include <cuda_runtime.h>

#define NUM_CAMS 6
#define C_FEAT   64
#define HF       16
#define WF       44
#define P_TOTAL  (8 * 128 * 128)                      // 131072
#define FEAT_ELEMS (NUM_CAMS * C_FEAT * HF * WF)      // 270336

#define PTS_PER_BLK 64
#define TASKS (PTS_PER_BLK * NUM_CAMS)                // 384

#define PK_BASE_MASK 0x7FFFF
#define PK_DX_BIT    (1 << 20)
#define PK_DY_BIT    (1 << 21)

// Precomputed per-camera projection (rows 0..2 of cam2img @ ego2cam)
__device__ float g_proj[NUM_CAMS][12];
// NHWC-transposed features: [cam][y][x][c], c contiguous (256B per pixel)
__device__ float g_feat_t[NUM_CAMS * HF * WF * C_FEAT];

// ---------------------------------------------------------------------------
// Prep: transpose (n,c,y,x) -> (n,y,x,c); block 0 also computes projections.
// ---------------------------------------------------------------------------
__global__ void prep_kernel(const float* __restrict__ in,
                            const float* __restrict__ ego2cam,
                            const float* __restrict__ cam2img) {
    int idx = blockIdx.x * blockDim.x + threadIdx.x;
    if (idx < FEAT_ELEMS) {
        int x = idx % WF;
        int t = idx / WF;
        int y = t % HF;  t /= HF;
        int c = t % C_FEAT;
        int n = t / C_FEAT;
        g_feat_t[(((n * HF + y) * WF) + x) * C_FEAT + c] = in[idx];
    }
    if (blockIdx.x == 0 && threadIdx.x < NUM_CAMS * 12) {
        int t = threadIdx.x;
        int n = t / 12;
        int r = (t % 12) / 4;
        int c = t % 4;
        float s = 0.f;
        #pragma unroll
        for (int k = 0; k < 4; k++)
            s += cam2img[n * 16 + r * 4 + k] * ego2cam[n * 16 + k * 4 + c];
        g_proj[n][r * 4 + c] = s;
    }
}

// ---------------------------------------------------------------------------
// Fuse (R8 block shape, ILP-fused cam loops):
//   Stage 1 : each (point,cam) projection once; weights (float4) + packed
//             corner int; cam bitmask via atomicOr (order-independent).
//   Stage 2 : 2 chunks of 32 points; each thread owns TWO points whose cam
//             loops are fused into one interleaved loop (2x MLP on the
//             LDS->LDG->FMA chain). 1/popc folded, no prescale pass.
//   Writeout: smem-staged per chunk, STG.128 along points.
// ---------------------------------------------------------------------------
__global__ void __launch_bounds__(256)
fuse_kernel(const float* __restrict__ vox, float* __restrict__ out) {
    __shared__ float4 s_w[TASKS];               // 6 KB    [n*64+pt]
    __shared__ int    s_pk[TASKS];              // 1.5 KB  [n*64+pt]
    __shared__ int    s_mask[PTS_PER_BLK];      // 256 B
    __shared__ float  s_out[32][65];            // 8.25 KB, padded rows

    int tid   = threadIdx.x;
    int pbase = blockIdx.x * PTS_PER_BLK;

    if (tid < PTS_PER_BLK) s_mask[tid] = 0;
    __syncthreads();

    // ---------------- Stage 1: projections, once per (point, cam) ----------
    for (int task = tid; task < TASKS; task += 256) {
        int pt = task & (PTS_PER_BLK - 1);
        int n  = task >> 6;                      // 0..5  (task = n*64+pt)
        int p  = pbase + pt;

        float px = vox[p];
        float py = vox[P_TOTAL + p];
        float pz = vox[2 * P_TOTAL + p];

        const float* M = g_proj[n];
        float uu = M[0] * px + M[1] * py + M[2]  * pz + M[3];
        float vv = M[4] * px + M[5] * py + M[6]  * pz + M[7];
        float dd = M[8] * px + M[9] * py + M[10] * pz + M[11];

        float inv = 1.0f / (dd + 1e-6f);
        float u = uu * inv;
        float v = vv * inv;

        bool valid = (dd > 0.1f) && (u >= 0.f) && (u <= 703.f)
                                 && (v >= 0.f) && (v <= 255.f);
        if (valid) {
            float x = u * (1.0f / 16.0f);
            float y = v * (1.0f / 16.0f);
            float x0f = floorf(x);
            float y0f = floorf(y);
            float wx1 = x - x0f, wy1 = y - y0f;
            float wx0 = 1.f - wx1, wy0 = 1.f - wy1;
            int x0 = (int)x0f;
            int y0 = (int)y0f;

            int dxb = PK_DX_BIT, dyb = PK_DY_BIT;
            if (x0 + 1 >= WF) { wx1 = 0.f; dxb = 0; }
            if (y0 + 1 >= HF) { wy1 = 0.f; dyb = 0; }

            int base = ((n * HF + y0) * WF + x0) * C_FEAT;   // < 2^19
            s_w[task]  = make_float4(wx0 * wy0, wx1 * wy0, wx0 * wy1, wx1 * wy1);
            s_pk[task] = base | dxb | dyb;
            atomicOr(&s_mask[pt], 1 << n);
        }
    }
    __syncthreads();

    // ---------------- Stage 2 + writeout, 2 chunks of 32 points -------------
    int lane = tid & 31;
    int wrp  = tid >> 5;          // 0..7
    int half = lane >> 4;
    int l    = lane & 15;         // channel group
    const float* fB = g_feat_t + 4 * l;

    #pragma unroll
    for (int chunk = 0; chunk < 2; chunk++) {
        // Each thread owns two points; their cam loops are FUSED so the two
        // independent LDS->LDG->FMA chains interleave (2x MLP).
        int ptA = chunk * 32 + wrp * 4 + half;       // it=0 point
        int ptB = ptA + 2;                            // it=1 point
        int rowA = ptA - chunk * 32;
        int rowB = ptB - chunk * 32;

        float4 accA = make_float4(0.f, 0.f, 0.f, 0.f);
        float4 accB = make_float4(0.f, 0.f, 0.f, 0.f);

        int mA = s_mask[ptA];
        int mB = s_mask[ptB];
        float rdenA = 1.0f / (float)__popc(mA | (mA == 0));
        float rdenB = 1.0f / (float)__popc(mB | (mB == 0));

        while (mA | mB) {
            // ---- issue A's loads ----
            float4 wgA; int baseA = 0, dxA = 0, dyA = 0; bool doA = (mA != 0);
            if (doA) {
                int n = __ffs(mA) - 1;
                mA &= mA - 1;
                int idx = n * PTS_PER_BLK + ptA;
                wgA = s_w[idx];
                int pk = s_pk[idx];
                baseA = pk & PK_BASE_MASK;
                dxA = (pk & PK_DX_BIT) ? C_FEAT : 0;
                dyA = (pk & PK_DY_BIT) ? WF * C_FEAT : 0;
            }
            // ---- issue B's loads ----
            float4 wgB; int baseB = 0, dxB = 0, dyB = 0; bool doB = (mB != 0);
            if (doB) {
                int n = __ffs(mB) - 1;
                mB &= mB - 1;
                int idx = n * PTS_PER_BLK + ptB;
                wgB = s_w[idx];
                int pk = s_pk[idx];
                baseB = pk & PK_BASE_MASK;
                dxB = (pk & PK_DX_BIT) ? C_FEAT : 0;
                dyB = (pk & PK_DY_BIT) ? WF * C_FEAT : 0;
            }

            if (doA) {
                float4 a = *(const float4*)(fB + baseA);
                float4 b = *(const float4*)(fB + baseA + dxA);
                float4 g = *(const float4*)(fB + baseA + dyA);
                float4 h = *(const float4*)(fB + baseA + dyA + dxA);
                accA.x = fmaf(wgA.x, a.x, fmaf(wgA.y, b.x, fmaf(wgA.z, g.x, fmaf(wgA.w, h.x, accA.x))));
                accA.y = fmaf(wgA.x, a.y, fmaf(wgA.y, b.y, fmaf(wgA.z, g.y, fmaf(wgA.w, h.y, accA.y))));
                accA.z = fmaf(wgA.x, a.z, fmaf(wgA.y, b.z, fmaf(wgA.z, g.z, fmaf(wgA.w, h.z, accA.z))));
                accA.w = fmaf(wgA.x, a.w, fmaf(wgA.y, b.w, fmaf(wgA.z, g.w, fmaf(wgA.w, h.w, accA.w))));
            }
            if (doB) {
                float4 a = *(const float4*)(fB + baseB);
                float4 b = *(const float4*)(fB + baseB + dxB);
                float4 g = *(const float4*)(fB + baseB + dyB);
                float4 h = *(const float4*)(fB + baseB + dyB + dxB);
                accB.x = fmaf(wgB.x, a.x, fmaf(wgB.y, b.x, fmaf(wgB.z, g.x, fmaf(wgB.w, h.x, accB.x))));
                accB.y = fmaf(wgB.x, a.y, fmaf(wgB.y, b.y, fmaf(wgB.z, g.y, fmaf(wgB.w, h.y, accB.y))));
                accB.z = fmaf(wgB.x, a.z, fmaf(wgB.y, b.z, fmaf(wgB.z, g.z, fmaf(wgB.w, h.z, accB.z))));
                accB.w = fmaf(wgB.x, a.w, fmaf(wgB.y, b.w, fmaf(wgB.z, g.w, fmaf(wgB.w, h.w, accB.w))));
            }
        }

        // scalar STS (row stride 65 floats: not 16B aligned for odd rows)
        s_out[rowA][4 * l + 0] = accA.x * rdenA;
        s_out[rowA][4 * l + 1] = accA.y * rdenA;
        s_out[rowA][4 * l + 2] = accA.z * rdenA;
        s_out[rowA][4 * l + 3] = accA.w * rdenA;
        s_out[rowB][4 * l + 0] = accB.x * rdenB;
        s_out[rowB][4 * l + 1] = accB.y * rdenB;
        s_out[rowB][4 * l + 2] = accB.z * rdenB;
        s_out[rowB][4 * l + 3] = accB.w * rdenB;

        __syncthreads();

        // Coalesced vectorized writeout of this 32-point chunk:
        // 64 channels x 32 points, STG.128 along the point dimension.
        #pragma unroll
        for (int k = 0; k < 2; k++) {
            int flat = k * 256 + tid;       // 0..511 float4 tiles
            int c = flat >> 3;              // 0..63
            int q = flat & 7;               // point quad 0..7
            float4 r;
            r.x = s_out[4 * q + 0][c];
            r.y = s_out[4 * q + 1][c];
            r.z = s_out[4 * q + 2][c];
            r.w = s_out[4 * q + 3][c];
            *(float4*)(out + c * P_TOTAL + pbase + chunk * 32 + 4 * q) = r;
        }

        __syncthreads();   // protect s_out before next chunk's STS
    }
}

// ---------------------------------------------------------------------------
extern "C" void kernel_launch(void* const* d_in, const int* in_sizes, int n_in,
                              void* d_out, int out_size) {
    const float* img_feats = (const float*)d_in[0];   // (6,64,16,44)
    const float* ego2cam   = (const float*)d_in[1];   // (6,4,4)
    const float* cam2img   = (const float*)d_in[2];   // (6,4,4)
    const float* vox       = (const float*)d_in[3];   // (3,8,128,128)
    float* out = (float*)d_out;                       // (1,64,8,128,128)

    prep_kernel<<<(FEAT_ELEMS + 255) / 256, 256>>>(img_feats, ego2cam, cam2img);
    fuse_kernel<<<P_TOTAL / PTS_PER_BLK, 256>>>(vox, out);
}